// round 1
// baseline (speedup 1.0000x reference)
#include <cuda_runtime.h>
#include <math.h>

#define WIDTH 128
#define NMAX  50176   // nodes (50000 actual, padded)

// ---- scratch (device globals: no allocation allowed) ----
__device__ float g_xx[NMAX * WIDTH];   // LN(pre(x))
__device__ float g_Q [NMAX * WIDTH];   // per-node q projection (+folded bias)
__device__ float g_K [NMAX * WIDTH];
__device__ float g_V [NMAX * WIDTH];   // pre-gelu v projection
__device__ float g_X2[NMAX * WIDTH];   // gelu(msg0(xx)) then += edge aggregation
__device__ float g_T [3 * 34 * WIDTH]; // remix-of-embedding lookup tables

__device__ __forceinline__ float gelu1(float x) {
    return 0.5f * x * (1.0f + erff(x * 0.7071067811865475f));
}

// ============================================================================
// Tiny precompute: T[j][row][o] = xw_c * scale_{e|v} * (emb_c[row_local] @ remix_j_w)[o]
// rows 0..33 = concat of the 4 vocab tables (sizes 6,7,3,18)
// ============================================================================
__global__ void k_tables(const float* __restrict__ r0w, const float* __restrict__ r1w,
                         const float* __restrict__ r2w,
                         const float* __restrict__ e0, const float* __restrict__ e1,
                         const float* __restrict__ e2, const float* __restrict__ e3,
                         const float* __restrict__ einit, const float* __restrict__ init0)
{
    int j = blockIdx.x;        // 0..2 (remix index)
    int r = blockIdx.y;        // 0..33 (concat row)
    int o = threadIdx.x;       // 0..127
    int c, lr;
    if (r < 6)       { c = 0; lr = r; }
    else if (r < 13) { c = 1; lr = r - 6; }
    else if (r < 16) { c = 2; lr = r - 13; }
    else             { c = 3; lr = r - 16; }
    const float* emb = (c == 0) ? e0 : (c == 1) ? e1 : (c == 2) ? e2 : e3;
    const float* rw  = (j == 0) ? r0w : (j == 1) ? r1w : r2w;

    __shared__ float er[64];
    if (o < 64) er[o] = emb[lr * 64 + o];
    __syncthreads();

    float s = 0.0f;
#pragma unroll
    for (int m = 0; m < 64; m++) s += er[m] * rw[m * WIDTH + o];

    float es = expf(einit[0]) + expf(einit[1]) + expf(einit[2]) + expf(einit[3]);
    float xw = expf(einit[c]) * rsqrtf(es);
    float sf = expf((j == 2) ? init0[3] : init0[2]);   // scale_v for remix2, scale_e else
    g_T[(j * 34 + r) * WIDTH + o] = s * xw * sf;
}

// ============================================================================
// Shared 64x128 (K=128) fp32 GEMM tile body. 256 threads.
// Thread (tr=tid/32, tc=tid%32) owns acc[8][4] = rows r0+tr*8..+7, cols tc*4..+3
// ============================================================================
__device__ __forceinline__ void gemm_body(const float* __restrict__ A,
                                          const float* __restrict__ W,
                                          int n, int r0, float acc[8][4])
{
    __shared__ float As[64][16];
    __shared__ float Ws[16][128];
    int tid = threadIdx.x;
    int tr = tid >> 5, tc = tid & 31;

#pragma unroll
    for (int i = 0; i < 8; i++)
#pragma unroll
        for (int jj = 0; jj < 4; jj++) acc[i][jj] = 0.0f;

    for (int k0 = 0; k0 < 128; k0 += 16) {
        // A tile: 64x16, one float4 per thread
        int ar = tid >> 2;
        int ac = (tid & 3) << 2;
        int grow = r0 + ar;
        float4 av = make_float4(0.f, 0.f, 0.f, 0.f);
        if (grow < n) av = *(const float4*)&A[grow * WIDTH + k0 + ac];
        *(float4*)&As[ar][ac] = av;
        // W tile: 16x128, two float4 per thread (contiguous per sub-pass)
#pragma unroll
        for (int q = 0; q < 2; q++) {
            int s  = q * 256 + tid;      // 0..511
            int kk = s >> 5;
            int c4 = (s & 31) << 2;
            *(float4*)&Ws[kk][c4] = *(const float4*)&W[(k0 + kk) * WIDTH + c4];
        }
        __syncthreads();
#pragma unroll
        for (int kk = 0; kk < 16; kk++) {
            float4 bv = *(float4*)&Ws[kk][tc << 2];
#pragma unroll
            for (int i = 0; i < 8; i++) {
                float a = As[tr * 8 + i][kk];
                acc[i][0] += a * bv.x;
                acc[i][1] += a * bv.y;
                acc[i][2] += a * bv.z;
                acc[i][3] += a * bv.w;
            }
        }
        __syncthreads();
    }
}

// ============================================================================
// pre: xx = LayerNorm(x @ pre_w + pre_b)   (one warp spans a full 128-wide row)
// ============================================================================
__global__ void __launch_bounds__(256) k_pre(const float* __restrict__ x,
                                             const float* __restrict__ w,
                                             const float* __restrict__ b, int n)
{
    int r0 = blockIdx.x * 64;
    float acc[8][4];
    gemm_body(x, w, n, r0, acc);

    int tr = threadIdx.x >> 5, tc = threadIdx.x & 31;
    float4 bb = *(const float4*)&b[tc << 2];
#pragma unroll
    for (int i = 0; i < 8; i++) {
        int row = r0 + tr * 8 + i;
        float v0 = acc[i][0] + bb.x;
        float v1 = acc[i][1] + bb.y;
        float v2 = acc[i][2] + bb.z;
        float v3 = acc[i][3] + bb.w;
        float s1 = v0 + v1 + v2 + v3;
        float s2 = v0 * v0 + v1 * v1 + v2 * v2 + v3 * v3;
#pragma unroll
        for (int m = 16; m; m >>= 1) {
            s1 += __shfl_xor_sync(0xffffffffu, s1, m);
            s2 += __shfl_xor_sync(0xffffffffu, s2, m);
        }
        float mean = s1 * (1.0f / 128.0f);
        float var  = s2 * (1.0f / 128.0f) - mean * mean;
        float rstd = rsqrtf(var + 1e-5f);
        if (row < n) {
            float4 o = make_float4((v0 - mean) * rstd, (v1 - mean) * rstd,
                                   (v2 - mean) * rstd, (v3 - mean) * rstd);
            *(float4*)&g_xx[row * WIDTH + (tc << 2)] = o;
        }
    }
}

// ============================================================================
// QKVM: blockIdx.y selects the projection.
//   0: Q = xx@msg1_w + msg1_b + scale_e*remix0_b
//   1: K = xx@msg2_w + msg2_b + scale_e*remix1_b
//   2: V = xx@msg3_w + msg3_b + scale_v*remix2_b   (gelu deferred to edge phase)
//   3: X2 = gelu(xx@msg0_w + msg0_b)
// ============================================================================
__global__ void __launch_bounds__(256) k_qkvm(
    const float* __restrict__ msg0_w, const float* __restrict__ msg0_b,
    const float* __restrict__ msg1_w, const float* __restrict__ msg1_b,
    const float* __restrict__ msg2_w, const float* __restrict__ msg2_b,
    const float* __restrict__ msg3_w, const float* __restrict__ msg3_b,
    const float* __restrict__ remix0_b, const float* __restrict__ remix1_b,
    const float* __restrict__ remix2_b, const float* __restrict__ init0, int n)
{
    int cb = blockIdx.y;
    const float* W; const float* b1; const float* b2; float* out;
    float sc = 0.0f; int do_gelu = 0;
    float sc_e = expf(init0[2]);
    float sc_v = expf(init0[3]);
    if (cb == 0)      { W = msg1_w; b1 = msg1_b; b2 = remix0_b; sc = sc_e; out = g_Q; }
    else if (cb == 1) { W = msg2_w; b1 = msg2_b; b2 = remix1_b; sc = sc_e; out = g_K; }
    else if (cb == 2) { W = msg3_w; b1 = msg3_b; b2 = remix2_b; sc = sc_v; out = g_V; }
    else              { W = msg0_w; b1 = msg0_b; b2 = 0;        sc = 0.f;  out = g_X2; do_gelu = 1; }

    int r0 = blockIdx.x * 64;
    float acc[8][4];
    gemm_body(g_xx, W, n, r0, acc);

    int tr = threadIdx.x >> 5, tc = threadIdx.x & 31;
    float4 bb = *(const float4*)&b1[tc << 2];
    if (b2) {
        float4 b2v = *(const float4*)&b2[tc << 2];
        bb.x += sc * b2v.x; bb.y += sc * b2v.y; bb.z += sc * b2v.z; bb.w += sc * b2v.w;
    }
#pragma unroll
    for (int i = 0; i < 8; i++) {
        int row = r0 + tr * 8 + i;
        if (row >= n) continue;
        float v0 = acc[i][0] + bb.x;
        float v1 = acc[i][1] + bb.y;
        float v2 = acc[i][2] + bb.z;
        float v3 = acc[i][3] + bb.w;
        if (do_gelu) { v0 = gelu1(v0); v1 = gelu1(v1); v2 = gelu1(v2); v3 = gelu1(v3); }
        *(float4*)&out[row * WIDTH + (tc << 2)] = make_float4(v0, v1, v2, v3);
    }
}

// ============================================================================
// Edge phase: one warp per edge, lane owns 4 columns.
//   q = Q[dst] + T0[rows];  k = K[src] + T1[rows];  v = gelu(V[src] + T2[rows])
//   att_h = exp( (q_h . k_h)/8 * init0[0] + init0[1] ),  msg = v * att_h
//   X2[dst] += msg  (red.global.add.v4.f32)
// ============================================================================
__global__ void __launch_bounds__(256) k_edge(const int* __restrict__ ei,
                                              const int* __restrict__ ea,
                                              const float* __restrict__ init0, int e)
{
    int gw = (int)((blockIdx.x * blockDim.x + threadIdx.x) >> 5);
    if (gw >= e) return;
    int lane = threadIdx.x & 31;

    int src = ei[gw];
    int dst = ei[e + gw];
    int r0 = ea[gw * 4 + 0];
    int r1 = 6 + ea[gw * 4 + 1];
    int r2 = 13 + ea[gw * 4 + 2];
    int r3 = 16 + ea[gw * 4 + 3];

    const float4* T = (const float4*)g_T;   // [3][34][32] float4
#define TROW(j, r) T[((j) * 34 + (r)) * 32 + lane]
    float4 a0 = TROW(0, r0), a1 = TROW(0, r1), a2 = TROW(0, r2), a3 = TROW(0, r3);
    float4 re0 = make_float4(a0.x + a1.x + a2.x + a3.x, a0.y + a1.y + a2.y + a3.y,
                             a0.z + a1.z + a2.z + a3.z, a0.w + a1.w + a2.w + a3.w);
    a0 = TROW(1, r0); a1 = TROW(1, r1); a2 = TROW(1, r2); a3 = TROW(1, r3);
    float4 re1 = make_float4(a0.x + a1.x + a2.x + a3.x, a0.y + a1.y + a2.y + a3.y,
                             a0.z + a1.z + a2.z + a3.z, a0.w + a1.w + a2.w + a3.w);
    a0 = TROW(2, r0); a1 = TROW(2, r1); a2 = TROW(2, r2); a3 = TROW(2, r3);
    float4 re2 = make_float4(a0.x + a1.x + a2.x + a3.x, a0.y + a1.y + a2.y + a3.y,
                             a0.z + a1.z + a2.z + a3.z, a0.w + a1.w + a2.w + a3.w);
#undef TROW

    int c4 = lane << 2;
    float4 qv = *(const float4*)&g_Q[dst * WIDTH + c4];
    float4 kv = *(const float4*)&g_K[src * WIDTH + c4];
    float4 vv = *(const float4*)&g_V[src * WIDTH + c4];
    qv.x += re0.x; qv.y += re0.y; qv.z += re0.z; qv.w += re0.w;
    kv.x += re1.x; kv.y += re1.y; kv.z += re1.z; kv.w += re1.w;
    float g0 = gelu1(vv.x + re2.x);
    float g1 = gelu1(vv.y + re2.y);
    float g2 = gelu1(vv.z + re2.z);
    float g3 = gelu1(vv.w + re2.w);

    float s = qv.x * kv.x + qv.y * kv.y + qv.z * kv.z + qv.w * kv.w;
#pragma unroll
    for (int m = 8; m; m >>= 1) s += __shfl_xor_sync(0xffffffffu, s, m);
    // lanes 0-15 hold head0 sum, lanes 16-31 head1 sum

    float att = expf(s * 0.125f * init0[0] + init0[1]);
    float m0 = g0 * att, m1 = g1 * att, m2 = g2 * att, m3 = g3 * att;

    float* dptr = &g_X2[dst * WIDTH + c4];
    asm volatile("red.global.add.v4.f32 [%0], {%1,%2,%3,%4};"
                 :: "l"(dptr), "f"(m0), "f"(m1), "f"(m2), "f"(m3) : "memory");
}

// ============================================================================
// post: out = x + (X2 @ post_w + post_b)
// ============================================================================
__global__ void __launch_bounds__(256) k_post(const float* __restrict__ w,
                                              const float* __restrict__ b,
                                              const float* __restrict__ x,
                                              float* __restrict__ out, int n)
{
    int r0 = blockIdx.x * 64;
    float acc[8][4];
    gemm_body(g_X2, w, n, r0, acc);

    int tr = threadIdx.x >> 5, tc = threadIdx.x & 31;
    float4 bb = *(const float4*)&b[tc << 2];
#pragma unroll
    for (int i = 0; i < 8; i++) {
        int row = r0 + tr * 8 + i;
        if (row >= n) continue;
        float4 xv = *(const float4*)&x[row * WIDTH + (tc << 2)];
        float4 o = make_float4(xv.x + acc[i][0] + bb.x, xv.y + acc[i][1] + bb.y,
                               xv.z + acc[i][2] + bb.z, xv.w + acc[i][3] + bb.w);
        *(float4*)&out[row * WIDTH + (tc << 2)] = o;
    }
}

extern "C" void kernel_launch(void* const* d_in, const int* in_sizes, int n_in,
                              void* d_out, int out_size)
{
    const float* x        = (const float*)d_in[0];
    const int*   ei       = (const int*)  d_in[1];
    const int*   ea       = (const int*)  d_in[2];
    const float* pre_w    = (const float*)d_in[3];
    const float* pre_b    = (const float*)d_in[4];
    const float* msg0_w   = (const float*)d_in[5];
    const float* msg0_b   = (const float*)d_in[6];
    const float* msg1_w   = (const float*)d_in[7];
    const float* msg1_b   = (const float*)d_in[8];
    const float* msg2_w   = (const float*)d_in[9];
    const float* msg2_b   = (const float*)d_in[10];
    const float* msg3_w   = (const float*)d_in[11];
    const float* msg3_b   = (const float*)d_in[12];
    const float* remix0_w = (const float*)d_in[13];
    const float* remix0_b = (const float*)d_in[14];
    const float* remix1_w = (const float*)d_in[15];
    const float* remix1_b = (const float*)d_in[16];
    const float* remix2_w = (const float*)d_in[17];
    const float* remix2_b = (const float*)d_in[18];
    const float* post_w   = (const float*)d_in[19];
    const float* post_b   = (const float*)d_in[20];
    const float* emb0     = (const float*)d_in[21];
    const float* emb1     = (const float*)d_in[22];
    const float* emb2     = (const float*)d_in[23];
    const float* emb3     = (const float*)d_in[24];
    const float* einit    = (const float*)d_in[25];
    const float* init0    = (const float*)d_in[26];

    int n = in_sizes[0] / WIDTH;
    int e = in_sizes[1] / 2;

    dim3 tg(3, 34);
    k_tables<<<tg, 128>>>(remix0_w, remix1_w, remix2_w, emb0, emb1, emb2, emb3, einit, init0);

    int gr = (n + 63) / 64;
    k_pre<<<gr, 256>>>(x, pre_w, pre_b, n);

    dim3 qg(gr, 4);
    k_qkvm<<<qg, 256>>>(msg0_w, msg0_b, msg1_w, msg1_b, msg2_w, msg2_b,
                        msg3_w, msg3_b, remix0_b, remix1_b, remix2_b, init0, n);

    k_edge<<<(e + 7) / 8, 256>>>(ei, ea, init0, e);

    k_post<<<gr, 256>>>(post_w, post_b, x, (float*)d_out, n);
}